// round 2
// baseline (speedup 1.0000x reference)
#include <cuda_runtime.h>

#define TT  15
#define C1I 6
#define HI  224
#define WI  224
#define C1O 30
#define HP  114
#define WP  114
#define C2O 240
#define HO  112
#define WO  112

typedef unsigned long long ull;

#define PACK2(d, lo, hi) \
    asm("mov.b64 %0, {%1, %2};" : "=l"(d) : "f"(lo), "f"(hi))
#define UNPACK2(lo, hi, s) \
    asm("mov.b64 {%0, %1}, %2;" : "=f"(lo), "=f"(hi) : "l"(s))
#define FMA2(d, a, b) \
    asm("fma.rn.f32x2 %0, %1, %2, %0;" : "+l"(d) : "l"(a), "l"(b))

// Padded, pooled layer-1 spike map: (T, 30, 114, 114), border = 0 (pad 1).
__device__ float g_spk1[(size_t)TT * C1O * HP * WP];

// ---------------------------------------------------------------------------
// Kernel 1: conv1 (5x5, pad 2) + fire(15) + maxpool 2x2 + pad 1, fused.
// pooled spike = (max of the 4 conv potentials) > 15.
// ---------------------------------------------------------------------------
__global__ __launch_bounds__(256) void k_conv1(const float* __restrict__ in,
                                               const float* __restrict__ w1) {
    extern __shared__ float smem[];
    float* sIn = smem;                 // [6][36][37]
    float* sW  = smem + 6 * 36 * 37;   // [30*6*25] = 4500

    const int t   = blockIdx.z;
    const int X0  = blockIdx.x * 16;
    const int Y0  = blockIdx.y * 16;
    const int tid = threadIdx.x;

    for (int i = tid; i < 4500; i += 256) sW[i] = w1[i];

    const float* inT = in + (size_t)t * (C1I * HI * WI);
    for (int i = tid; i < 6 * 36 * 36; i += 256) {
        int c  = i % 36;
        int r  = (i / 36) % 36;
        int ic = i / (36 * 36);
        int gy = 2 * Y0 - 2 + r;
        int gx = 2 * X0 - 2 + c;
        float v = 0.0f;
        if ((unsigned)gy < (unsigned)HI && (unsigned)gx < (unsigned)WI)
            v = inT[(ic * HI + gy) * WI + gx];
        sIn[(ic * 36 + r) * 37 + c] = v;
    }
    __syncthreads();

    const int tx = tid & 15;
    const int ty = tid >> 4;
    float* outp = g_spk1 + (size_t)t * C1O * HP * WP
                + (size_t)(Y0 + ty + 1) * WP + (X0 + tx + 1);

    for (int cg = 0; cg < 5; cg++) {
        float pot[6][4];
#pragma unroll
        for (int u = 0; u < 6; u++)
#pragma unroll
            for (int q = 0; q < 4; q++) pot[u][q] = 0.0f;

        for (int ic = 0; ic < 6; ic++) {
            float p[6][6];
#pragma unroll
            for (int r = 0; r < 6; r++)
#pragma unroll
                for (int c = 0; c < 6; c++)
                    p[r][c] = sIn[(ic * 36 + 2 * ty + r) * 37 + 2 * tx + c];

#pragma unroll
            for (int u = 0; u < 6; u++) {
                const float* w = sW + ((cg * 6 + u) * 6 + ic) * 25;
#pragma unroll
                for (int kh = 0; kh < 5; kh++)
#pragma unroll
                    for (int kw = 0; kw < 5; kw++) {
                        float wv = w[kh * 5 + kw];
                        pot[u][0] = fmaf(p[kh    ][kw    ], wv, pot[u][0]);
                        pot[u][1] = fmaf(p[kh    ][kw + 1], wv, pot[u][1]);
                        pot[u][2] = fmaf(p[kh + 1][kw    ], wv, pot[u][2]);
                        pot[u][3] = fmaf(p[kh + 1][kw + 1], wv, pot[u][3]);
                    }
            }
        }
#pragma unroll
        for (int u = 0; u < 6; u++) {
            float m = fmaxf(fmaxf(pot[u][0], pot[u][1]),
                            fmaxf(pot[u][2], pot[u][3]));
            outp[(size_t)(cg * 6 + u) * HP * WP] = (m > 15.0f) ? 1.0f : 0.0f;
        }
    }
}

// ---------------------------------------------------------------------------
// Kernel 2: conv2 (3x3, 30->240) + fire(10), packed f32x2 FMA.
// Block (128 thr): 16x16 px tile, 16 oc. Thread: 8 px (as 4 f32x2 pairs) x 4 oc.
// Thread map: ty = tid&15 (lane-minor -> conflict-free LDS.128 with stride 20),
//             qx = (tid>>4)&1, g = tid>>5.
// ---------------------------------------------------------------------------
#define S2 20   // sIn row stride (floats): 16B-aligned rows, conflict-free phases

__global__ __launch_bounds__(128) void k_conv2(const float* __restrict__ w2,
                                               float* __restrict__ spk,
                                               float* __restrict__ pot) {
    extern __shared__ float smem[];
    float* sIn = smem;                   // [30][18][20] = 10800 floats
    float* sW  = smem + 30 * 18 * S2;    // [16][30][3][4] = 5760 floats

    const int t   = blockIdx.z / 15;
    const int ocb = (blockIdx.z % 15) * 16;
    const int X0  = blockIdx.x * 16;
    const int Y0  = blockIdx.y * 16;
    const int tid = threadIdx.x;

    // Weights, padded to 4 floats per (oc,ic,kh) row for LDS.128.
    const float* wsrc = w2 + (size_t)ocb * 270;
    for (int i = tid; i < 16 * 270; i += 128) {
        int oc = i / 270, r = i % 270;
        int ic = r / 9, k = r % 9;
        sW[((oc * 30 + ic) * 3 + k / 3) * 4 + (k % 3)] = wsrc[i];
    }

    // Input tile: 30ch x 18x18 from padded pooled spike map.
    const float* sp = g_spk1 + (size_t)t * (C1O * HP * WP);
    for (int i = tid; i < 30 * 18 * 18; i += 128) {
        int c  = i % 18;
        int r  = (i / 18) % 18;
        int ic = i / (18 * 18);
        sIn[(ic * 18 + r) * S2 + c] = sp[(ic * HP + Y0 + r) * WP + X0 + c];
    }
    __syncthreads();

    const int ty = tid & 15;
    const int qx = (tid >> 4) & 1;
    const int g  = tid >> 5;

    ull acc[4][4];
#pragma unroll
    for (int u = 0; u < 4; u++)
#pragma unroll
        for (int j = 0; j < 4; j++) acc[u][j] = 0ULL;

    for (int ic = 0; ic < 30; ic++) {
        const float* vb = sIn + (ic * 18 + ty) * S2 + 8 * qx;
#pragma unroll
        for (int kh = 0; kh < 3; kh++) {
            float4 A = *(const float4*)(vb + kh * S2);
            float4 B = *(const float4*)(vb + kh * S2 + 4);
            float2 C = *(const float2*)(vb + kh * S2 + 8);
            ull p0, p1, p2, p3, p4, s0, s1, s2, s3;
            PACK2(p0, A.x, A.y); PACK2(p1, A.z, A.w);
            PACK2(p2, B.x, B.y); PACK2(p3, B.z, B.w);
            PACK2(p4, C.x, C.y);
            PACK2(s0, A.y, A.z); PACK2(s1, A.w, B.x);
            PACK2(s2, B.y, B.z); PACK2(s3, B.w, C.x);
#pragma unroll
            for (int u = 0; u < 4; u++) {
                float4 w = *(const float4*)(sW + (((g * 4 + u) * 30 + ic) * 3 + kh) * 4);
                ull W0, W1, W2;
                PACK2(W0, w.x, w.x); PACK2(W1, w.y, w.y); PACK2(W2, w.z, w.z);
                FMA2(acc[u][0], p0, W0); FMA2(acc[u][0], s0, W1); FMA2(acc[u][0], p1, W2);
                FMA2(acc[u][1], p1, W0); FMA2(acc[u][1], s1, W1); FMA2(acc[u][1], p2, W2);
                FMA2(acc[u][2], p2, W0); FMA2(acc[u][2], s2, W1); FMA2(acc[u][2], p3, W2);
                FMA2(acc[u][3], p3, W0); FMA2(acc[u][3], s3, W1); FMA2(acc[u][3], p4, W2);
            }
        }
    }

    const int y = Y0 + ty;
    const int x = X0 + 8 * qx;
#pragma unroll
    for (int u = 0; u < 4; u++) {
        int oc = ocb + g * 4 + u;
        size_t base = (((size_t)t * C2O + oc) * HO + y) * WO + x;
        float a[8];
        UNPACK2(a[0], a[1], acc[u][0]);
        UNPACK2(a[2], a[3], acc[u][1]);
        UNPACK2(a[4], a[5], acc[u][2]);
        UNPACK2(a[6], a[7], acc[u][3]);
        float4 sa, sb, pa, pb;
        sa.x = a[0] > 10.0f ? 1.0f : 0.0f;  pa.x = a[0] > 10.0f ? a[0] : 0.0f;
        sa.y = a[1] > 10.0f ? 1.0f : 0.0f;  pa.y = a[1] > 10.0f ? a[1] : 0.0f;
        sa.z = a[2] > 10.0f ? 1.0f : 0.0f;  pa.z = a[2] > 10.0f ? a[2] : 0.0f;
        sa.w = a[3] > 10.0f ? 1.0f : 0.0f;  pa.w = a[3] > 10.0f ? a[3] : 0.0f;
        sb.x = a[4] > 10.0f ? 1.0f : 0.0f;  pb.x = a[4] > 10.0f ? a[4] : 0.0f;
        sb.y = a[5] > 10.0f ? 1.0f : 0.0f;  pb.y = a[5] > 10.0f ? a[5] : 0.0f;
        sb.z = a[6] > 10.0f ? 1.0f : 0.0f;  pb.z = a[6] > 10.0f ? a[6] : 0.0f;
        sb.w = a[7] > 10.0f ? 1.0f : 0.0f;  pb.w = a[7] > 10.0f ? a[7] : 0.0f;
        *reinterpret_cast<float4*>(spk + base)     = sa;
        *reinterpret_cast<float4*>(spk + base + 4) = sb;
        *reinterpret_cast<float4*>(pot + base)     = pa;
        *reinterpret_cast<float4*>(pot + base + 4) = pb;
    }
}

// ---------------------------------------------------------------------------
extern "C" void kernel_launch(void* const* d_in, const int* in_sizes, int n_in,
                              void* d_out, int out_size) {
    const float* in = (const float*)d_in[0];
    const float* w1 = (const float*)d_in[1];
    const float* w2 = (const float*)d_in[2];
    // d_in[3] = max_layer, always 2 in this problem.

    float* spk = (float*)d_out;
    const size_t n2 = (size_t)TT * C2O * HO * WO;
    float* pot = spk + n2;

    // Zero the scratch spike map (gives us the pad-1 border for free).
    void* sp1 = nullptr;
    cudaGetSymbolAddress(&sp1, g_spk1);
    cudaMemsetAsync(sp1, 0, sizeof(g_spk1), 0);

    const int smem1 = (6 * 36 * 37 + 4500) * (int)sizeof(float);        // 49,968 B
    const int smem2 = (30 * 18 * S2 + 16 * 30 * 12) * (int)sizeof(float); // 66,240 B
    cudaFuncSetAttribute(k_conv1, cudaFuncAttributeMaxDynamicSharedMemorySize, smem1);
    cudaFuncSetAttribute(k_conv2, cudaFuncAttributeMaxDynamicSharedMemorySize, smem2);

    k_conv1<<<dim3(7, 7, TT), 256, smem1>>>(in, w1);
    k_conv2<<<dim3(7, 7, TT * 15), 128, smem2>>>(w2, spk, pot);
}

// round 3
// speedup vs baseline: 1.0107x; 1.0107x over previous
#include <cuda_runtime.h>

#define TT  15
#define C1I 6
#define HI  224
#define WI  224
#define C1O 30
#define HP  114
#define WP  114
#define C2O 240
#define HO  112
#define WO  112

typedef unsigned long long ull;

#define UNPACK2(lo, hi, s) \
    asm("mov.b64 {%0, %1}, %2;" : "=f"(lo), "=f"(hi) : "l"(s))
#define FMA2(d, a, b) \
    asm("fma.rn.f32x2 %0, %1, %2, %0;" : "+l"(d) : "l"(a), "l"(b))

// Padded, pooled layer-1 spike map: (T, 30, 114, 114), border = 0 (pad 1).
__device__ float g_spk1[(size_t)TT * C1O * HP * WP];
// Duplicated conv2 weights: [240][30][3][8] = {w0,w0,w1,w1,w2,w2,0,0}
__device__ float g_w2dup[(size_t)C2O * 30 * 3 * 8];

// ---------------------------------------------------------------------------
// Prep: duplicate conv2 weights for direct f32x2 operand loads.
// ---------------------------------------------------------------------------
__global__ __launch_bounds__(256) void k_dupw(const float* __restrict__ w2) {
    int i = blockIdx.x * 256 + threadIdx.x;     // row = (oc*30+ic)*3+kh
    if (i < C2O * 30 * 3) {
        const float* s = w2 + i * 3;
        float* d = g_w2dup + (size_t)i * 8;
        float w0 = s[0], w1 = s[1], w2v = s[2];
        d[0] = w0; d[1] = w0; d[2] = w1; d[3] = w1;
        d[4] = w2v; d[5] = w2v; d[6] = 0.0f; d[7] = 0.0f;
    }
}

// ---------------------------------------------------------------------------
// Kernel 1: conv1 (5x5, pad 2) + fire(15) + maxpool 2x2 + pad 1, fused.
// pooled spike = (max of the 4 conv potentials) > 15.
// ---------------------------------------------------------------------------
__global__ __launch_bounds__(256) void k_conv1(const float* __restrict__ in,
                                               const float* __restrict__ w1) {
    extern __shared__ float smem[];
    float* sIn = smem;                 // [6][36][37]
    float* sW  = smem + 6 * 36 * 37;   // [30*6*25] = 4500

    const int t   = blockIdx.z;
    const int X0  = blockIdx.x * 16;
    const int Y0  = blockIdx.y * 16;
    const int tid = threadIdx.x;

    for (int i = tid; i < 4500; i += 256) sW[i] = w1[i];

    const float* inT = in + (size_t)t * (C1I * HI * WI);
    for (int i = tid; i < 6 * 36 * 36; i += 256) {
        int c  = i % 36;
        int r  = (i / 36) % 36;
        int ic = i / (36 * 36);
        int gy = 2 * Y0 - 2 + r;
        int gx = 2 * X0 - 2 + c;
        float v = 0.0f;
        if ((unsigned)gy < (unsigned)HI && (unsigned)gx < (unsigned)WI)
            v = inT[(ic * HI + gy) * WI + gx];
        sIn[(ic * 36 + r) * 37 + c] = v;
    }
    __syncthreads();

    const int tx = tid & 15;
    const int ty = tid >> 4;
    float* outp = g_spk1 + (size_t)t * C1O * HP * WP
                + (size_t)(Y0 + ty + 1) * WP + (X0 + tx + 1);

    for (int cg = 0; cg < 5; cg++) {
        float pot[6][4];
#pragma unroll
        for (int u = 0; u < 6; u++)
#pragma unroll
            for (int q = 0; q < 4; q++) pot[u][q] = 0.0f;

        for (int ic = 0; ic < 6; ic++) {
            float p[6][6];
#pragma unroll
            for (int r = 0; r < 6; r++)
#pragma unroll
                for (int c = 0; c < 6; c++)
                    p[r][c] = sIn[(ic * 36 + 2 * ty + r) * 37 + 2 * tx + c];

#pragma unroll
            for (int u = 0; u < 6; u++) {
                const float* w = sW + ((cg * 6 + u) * 6 + ic) * 25;
#pragma unroll
                for (int kh = 0; kh < 5; kh++)
#pragma unroll
                    for (int kw = 0; kw < 5; kw++) {
                        float wv = w[kh * 5 + kw];
                        pot[u][0] = fmaf(p[kh    ][kw    ], wv, pot[u][0]);
                        pot[u][1] = fmaf(p[kh    ][kw + 1], wv, pot[u][1]);
                        pot[u][2] = fmaf(p[kh + 1][kw    ], wv, pot[u][2]);
                        pot[u][3] = fmaf(p[kh + 1][kw + 1], wv, pot[u][3]);
                    }
            }
        }
#pragma unroll
        for (int u = 0; u < 6; u++) {
            float m = fmaxf(fmaxf(pot[u][0], pot[u][1]),
                            fmaxf(pot[u][2], pot[u][3]));
            outp[(size_t)(cg * 6 + u) * HP * WP] = (m > 15.0f) ? 1.0f : 0.0f;
        }
    }
}

// ---------------------------------------------------------------------------
// Kernel 2: conv2 (3x3, 30->240) + fire(10), packed f32x2 FMA.
// Block (128 thr): 16x16 px tile, 24 oc. Thread: 8 px (4 pairs) x 6 oc.
// Activations: aligned LDS.128/LDS.64 into ull pairs (conflict-free, stride 20).
// Weights: broadcast LDG of pre-duplicated pairs (no smem, no packing movs).
// ---------------------------------------------------------------------------
#define S2 20   // sIn row stride in floats

__global__ __launch_bounds__(128) void k_conv2(float* __restrict__ spk,
                                               float* __restrict__ pot) {
    extern __shared__ float smem[];
    float* sIn = smem;                   // [30][18][20] = 10800 floats = 43.2KB

    const int t   = blockIdx.z / 10;
    const int ocb = (blockIdx.z % 10) * 24;
    const int X0  = blockIdx.x * 16;
    const int Y0  = blockIdx.y * 16;
    const int tid = threadIdx.x;

    // Input tile: 30ch x 18x18 from padded pooled spike map.
    const float* sp = g_spk1 + (size_t)t * (C1O * HP * WP);
    for (int i = tid; i < 30 * 18 * 18; i += 128) {
        int c  = i % 18;
        int r  = (i / 18) % 18;
        int ic = i / (18 * 18);
        sIn[(ic * 18 + r) * S2 + c] = sp[(ic * HP + Y0 + r) * WP + X0 + c];
    }
    __syncthreads();

    const int ty = tid & 15;
    const int qx = (tid >> 4) & 1;
    const int g  = tid >> 5;             // 4 groups x 6 oc = 24 oc

    ull acc[6][4];
#pragma unroll
    for (int u = 0; u < 6; u++)
#pragma unroll
        for (int j = 0; j < 4; j++) acc[u][j] = 0ULL;

    const float* wbase = g_w2dup + (size_t)(ocb + g * 6) * 30 * 24;

    for (int ic = 0; ic < 30; ic++) {
        const float* vb = sIn + (ic * 18 + ty) * S2 + 8 * qx;
        const float* wic = wbase + ic * 24;
#pragma unroll
        for (int kh = 0; kh < 3; kh++) {
            ulonglong2 ab = *(const ulonglong2*)(vb + kh * S2);      // p0,p1
            ulonglong2 cd = *(const ulonglong2*)(vb + kh * S2 + 4);  // p2,p3
            ull p4 = *(const ull*)(vb + kh * S2 + 8);
            ull p0 = ab.x, p1 = ab.y, p2 = cd.x, p3 = cd.y;
            ull s0 = (p0 >> 32) | (p1 << 32);
            ull s1 = (p1 >> 32) | (p2 << 32);
            ull s2 = (p2 >> 32) | (p3 << 32);
            ull s3 = (p3 >> 32) | (p4 << 32);
#pragma unroll
            for (int u = 0; u < 6; u++) {
                const ull* wp = (const ull*)(wic + (size_t)u * 30 * 24 + kh * 8);
                ulonglong2 w01 = *(const ulonglong2*)wp;   // (w0,w0),(w1,w1)
                ull W0 = w01.x, W1 = w01.y;
                ull W2 = wp[2];                            // (w2,w2)
                FMA2(acc[u][0], p0, W0); FMA2(acc[u][0], s0, W1); FMA2(acc[u][0], p1, W2);
                FMA2(acc[u][1], p1, W0); FMA2(acc[u][1], s1, W1); FMA2(acc[u][1], p2, W2);
                FMA2(acc[u][2], p2, W0); FMA2(acc[u][2], s2, W1); FMA2(acc[u][2], p3, W2);
                FMA2(acc[u][3], p3, W0); FMA2(acc[u][3], s3, W1); FMA2(acc[u][3], p4, W2);
            }
        }
    }

    const int y = Y0 + ty;
    const int x = X0 + 8 * qx;
#pragma unroll
    for (int u = 0; u < 6; u++) {
        int oc = ocb + g * 6 + u;
        size_t base = (((size_t)t * C2O + oc) * HO + y) * WO + x;
        float a[8];
        UNPACK2(a[0], a[1], acc[u][0]);
        UNPACK2(a[2], a[3], acc[u][1]);
        UNPACK2(a[4], a[5], acc[u][2]);
        UNPACK2(a[6], a[7], acc[u][3]);
        float4 sa, sb, pa, pb;
        sa.x = a[0] > 10.0f ? 1.0f : 0.0f;  pa.x = a[0] > 10.0f ? a[0] : 0.0f;
        sa.y = a[1] > 10.0f ? 1.0f : 0.0f;  pa.y = a[1] > 10.0f ? a[1] : 0.0f;
        sa.z = a[2] > 10.0f ? 1.0f : 0.0f;  pa.z = a[2] > 10.0f ? a[2] : 0.0f;
        sa.w = a[3] > 10.0f ? 1.0f : 0.0f;  pa.w = a[3] > 10.0f ? a[3] : 0.0f;
        sb.x = a[4] > 10.0f ? 1.0f : 0.0f;  pb.x = a[4] > 10.0f ? a[4] : 0.0f;
        sb.y = a[5] > 10.0f ? 1.0f : 0.0f;  pb.y = a[5] > 10.0f ? a[5] : 0.0f;
        sb.z = a[6] > 10.0f ? 1.0f : 0.0f;  pb.z = a[6] > 10.0f ? a[6] : 0.0f;
        sb.w = a[7] > 10.0f ? 1.0f : 0.0f;  pb.w = a[7] > 10.0f ? a[7] : 0.0f;
        *reinterpret_cast<float4*>(spk + base)     = sa;
        *reinterpret_cast<float4*>(spk + base + 4) = sb;
        *reinterpret_cast<float4*>(pot + base)     = pa;
        *reinterpret_cast<float4*>(pot + base + 4) = pb;
    }
}

// ---------------------------------------------------------------------------
extern "C" void kernel_launch(void* const* d_in, const int* in_sizes, int n_in,
                              void* d_out, int out_size) {
    const float* in = (const float*)d_in[0];
    const float* w1 = (const float*)d_in[1];
    const float* w2 = (const float*)d_in[2];
    // d_in[3] = max_layer, always 2 in this problem.

    float* spk = (float*)d_out;
    const size_t n2 = (size_t)TT * C2O * HO * WO;
    float* pot = spk + n2;

    void* sp1 = nullptr;
    cudaGetSymbolAddress(&sp1, g_spk1);
    cudaMemsetAsync(sp1, 0, sizeof(g_spk1), 0);

    const int smem1 = (6 * 36 * 37 + 4500) * (int)sizeof(float);   // 49,968 B
    const int smem2 = (30 * 18 * S2) * (int)sizeof(float);         // 43,200 B
    cudaFuncSetAttribute(k_conv1, cudaFuncAttributeMaxDynamicSharedMemorySize, smem1);
    cudaFuncSetAttribute(k_conv2, cudaFuncAttributeMaxDynamicSharedMemorySize, smem2);

    k_dupw<<<(C2O * 30 * 3 + 255) / 256, 256>>>(w2);
    k_conv1<<<dim3(7, 7, TT), 256, smem1>>>(in, w1);
    k_conv2<<<dim3(7, 7, TT * 10), 128, smem2>>>(spk, pot);
}

// round 4
// speedup vs baseline: 1.2678x; 1.2543x over previous
#include <cuda_runtime.h>

#define TT  15
#define C1I 6
#define HI  224
#define WI  224
#define C1O 30
#define HP  114
#define WP  114
#define C2O 240
#define HO  112
#define WO  112

// Padded, pooled layer-1 spike map: (T, 30, 114, 114), border = 0 (pad 1).
__device__ float g_spk1[(size_t)TT * C1O * HP * WP];

// ---------------------------------------------------------------------------
// Kernel 1: conv1 (5x5, pad 2) + fire(15) + maxpool 2x2 + pad 1, fused.
// pooled spike = (max of the 4 conv potentials) > 15.
// ---------------------------------------------------------------------------
__global__ __launch_bounds__(256) void k_conv1(const float* __restrict__ in,
                                               const float* __restrict__ w1) {
    extern __shared__ float smem[];
    float* sIn = smem;                 // [6][36][37]
    float* sW  = smem + 6 * 36 * 37;   // [30*6*25] = 4500

    const int t   = blockIdx.z;
    const int X0  = blockIdx.x * 16;
    const int Y0  = blockIdx.y * 16;
    const int tid = threadIdx.x;

    for (int i = tid; i < 4500; i += 256) sW[i] = w1[i];

    const float* inT = in + (size_t)t * (C1I * HI * WI);
    for (int i = tid; i < 6 * 36 * 36; i += 256) {
        int c  = i % 36;
        int r  = (i / 36) % 36;
        int ic = i / (36 * 36);
        int gy = 2 * Y0 - 2 + r;
        int gx = 2 * X0 - 2 + c;
        float v = 0.0f;
        if ((unsigned)gy < (unsigned)HI && (unsigned)gx < (unsigned)WI)
            v = inT[(ic * HI + gy) * WI + gx];
        sIn[(ic * 36 + r) * 37 + c] = v;
    }
    __syncthreads();

    const int tx = tid & 15;
    const int ty = tid >> 4;
    float* outp = g_spk1 + (size_t)t * C1O * HP * WP
                + (size_t)(Y0 + ty + 1) * WP + (X0 + tx + 1);

    for (int cg = 0; cg < 5; cg++) {
        float pot[6][4];
#pragma unroll
        for (int u = 0; u < 6; u++)
#pragma unroll
            for (int q = 0; q < 4; q++) pot[u][q] = 0.0f;

        for (int ic = 0; ic < 6; ic++) {
            float p[6][6];
#pragma unroll
            for (int r = 0; r < 6; r++)
#pragma unroll
                for (int c = 0; c < 6; c++)
                    p[r][c] = sIn[(ic * 36 + 2 * ty + r) * 37 + 2 * tx + c];

#pragma unroll
            for (int u = 0; u < 6; u++) {
                const float* w = sW + ((cg * 6 + u) * 6 + ic) * 25;
#pragma unroll
                for (int kh = 0; kh < 5; kh++)
#pragma unroll
                    for (int kw = 0; kw < 5; kw++) {
                        float wv = w[kh * 5 + kw];
                        pot[u][0] = fmaf(p[kh    ][kw    ], wv, pot[u][0]);
                        pot[u][1] = fmaf(p[kh    ][kw + 1], wv, pot[u][1]);
                        pot[u][2] = fmaf(p[kh + 1][kw    ], wv, pot[u][2]);
                        pot[u][3] = fmaf(p[kh + 1][kw + 1], wv, pot[u][3]);
                    }
            }
        }
#pragma unroll
        for (int u = 0; u < 6; u++) {
            float m = fmaxf(fmaxf(pot[u][0], pot[u][1]),
                            fmaxf(pot[u][2], pot[u][3]));
            outp[(size_t)(cg * 6 + u) * HP * WP] = (m > 15.0f) ? 1.0f : 0.0f;
        }
    }
}

// ---------------------------------------------------------------------------
// Kernel 2: conv2 (3x3, 30->240) + fire(10), scalar FFMA (dual fp32 ports).
// Block (256 thr): 16x16 px tile, 24 oc. Thread: 8 px x 3 oc (24 accums).
// Warp = ty(16) x qx(2); g = warp id -> weight LDS.128 is pure broadcast.
// Activation rows: stride-20 smem, LDS.128 quarter-warp phases conflict-free.
// ---------------------------------------------------------------------------
#define S2 20   // sIn row stride in floats

__global__ __launch_bounds__(256) void k_conv2(const float* __restrict__ w2,
                                               float* __restrict__ spk,
                                               float* __restrict__ pot) {
    extern __shared__ float smem[];
    float* sIn = smem;                   // [30][18][20] = 10800 floats (43.2KB)
    float* sW  = smem + 30 * 18 * S2;    // [24][30][3][4] = 8640 floats (34.6KB)

    const int t   = blockIdx.z / 10;
    const int ocb = (blockIdx.z % 10) * 24;
    const int X0  = blockIdx.x * 16;
    const int Y0  = blockIdx.y * 16;
    const int tid = threadIdx.x;

    // Weights for 24 oc, padded to 4 floats per (oc,ic,kh) row (LDS.128-able).
    const float* wsrc = w2 + (size_t)ocb * 270;
    for (int i = tid; i < 24 * 270; i += 256) {
        int oc = i / 270, r = i % 270;
        int ic = r / 9, k = r % 9;
        sW[((oc * 30 + ic) * 3 + k / 3) * 4 + (k % 3)] = wsrc[i];
    }

    // Input tile: 30ch x 18x18 from padded pooled spike map.
    const float* sp = g_spk1 + (size_t)t * (C1O * HP * WP);
    for (int i = tid; i < 30 * 18 * 18; i += 256) {
        int c  = i % 18;
        int r  = (i / 18) % 18;
        int ic = i / (18 * 18);
        sIn[(ic * 18 + r) * S2 + c] = sp[(ic * HP + Y0 + r) * WP + X0 + c];
    }
    __syncthreads();

    const int ty = tid & 15;
    const int qx = (tid >> 4) & 1;
    const int g  = tid >> 5;             // 8 warps x 3 oc = 24 oc

    float acc[3][8];
#pragma unroll
    for (int u = 0; u < 3; u++)
#pragma unroll
        for (int p = 0; p < 8; p++) acc[u][p] = 0.0f;

    const float* vbase = sIn + ty * S2 + 8 * qx;
    const float* wbase = sW + (size_t)(g * 3) * 30 * 12;

    for (int ic = 0; ic < 30; ic++) {
        const float* vb  = vbase + ic * 18 * S2;
        const float* wic = wbase + ic * 12;
#pragma unroll
        for (int kh = 0; kh < 3; kh++) {
            float4 A = *(const float4*)(vb + kh * S2);
            float4 B = *(const float4*)(vb + kh * S2 + 4);
            float2 C = *(const float2*)(vb + kh * S2 + 8);
            float v[10] = {A.x, A.y, A.z, A.w, B.x, B.y, B.z, B.w, C.x, C.y};
#pragma unroll
            for (int u = 0; u < 3; u++) {
                float4 w = *(const float4*)(wic + (size_t)u * 30 * 12 + kh * 4);
#pragma unroll
                for (int p = 0; p < 8; p++) {
                    acc[u][p] = fmaf(v[p],     w.x, acc[u][p]);
                    acc[u][p] = fmaf(v[p + 1], w.y, acc[u][p]);
                    acc[u][p] = fmaf(v[p + 2], w.z, acc[u][p]);
                }
            }
        }
    }

    const int y = Y0 + ty;
    const int x = X0 + 8 * qx;
#pragma unroll
    for (int u = 0; u < 3; u++) {
        int oc = ocb + g * 3 + u;
        size_t base = (((size_t)t * C2O + oc) * HO + y) * WO + x;
        float4 sa, sb, pa, pb;
        sa.x = acc[u][0] > 10.0f ? 1.0f : 0.0f;  pa.x = acc[u][0] > 10.0f ? acc[u][0] : 0.0f;
        sa.y = acc[u][1] > 10.0f ? 1.0f : 0.0f;  pa.y = acc[u][1] > 10.0f ? acc[u][1] : 0.0f;
        sa.z = acc[u][2] > 10.0f ? 1.0f : 0.0f;  pa.z = acc[u][2] > 10.0f ? acc[u][2] : 0.0f;
        sa.w = acc[u][3] > 10.0f ? 1.0f : 0.0f;  pa.w = acc[u][3] > 10.0f ? acc[u][3] : 0.0f;
        sb.x = acc[u][4] > 10.0f ? 1.0f : 0.0f;  pb.x = acc[u][4] > 10.0f ? acc[u][4] : 0.0f;
        sb.y = acc[u][5] > 10.0f ? 1.0f : 0.0f;  pb.y = acc[u][5] > 10.0f ? acc[u][5] : 0.0f;
        sb.z = acc[u][6] > 10.0f ? 1.0f : 0.0f;  pb.z = acc[u][6] > 10.0f ? acc[u][6] : 0.0f;
        sb.w = acc[u][7] > 10.0f ? 1.0f : 0.0f;  pb.w = acc[u][7] > 10.0f ? acc[u][7] : 0.0f;
        *reinterpret_cast<float4*>(spk + base)     = sa;
        *reinterpret_cast<float4*>(spk + base + 4) = sb;
        *reinterpret_cast<float4*>(pot + base)     = pa;
        *reinterpret_cast<float4*>(pot + base + 4) = pb;
    }
}

// ---------------------------------------------------------------------------
extern "C" void kernel_launch(void* const* d_in, const int* in_sizes, int n_in,
                              void* d_out, int out_size) {
    const float* in = (const float*)d_in[0];
    const float* w1 = (const float*)d_in[1];
    const float* w2 = (const float*)d_in[2];
    // d_in[3] = max_layer, always 2 in this problem.

    float* spk = (float*)d_out;
    const size_t n2 = (size_t)TT * C2O * HO * WO;
    float* pot = spk + n2;

    void* sp1 = nullptr;
    cudaGetSymbolAddress(&sp1, g_spk1);
    cudaMemsetAsync(sp1, 0, sizeof(g_spk1), 0);

    const int smem1 = (6 * 36 * 37 + 4500) * (int)sizeof(float);            // 49,968 B
    const int smem2 = (30 * 18 * S2 + 24 * 30 * 12) * (int)sizeof(float);   // 77,760 B
    cudaFuncSetAttribute(k_conv1, cudaFuncAttributeMaxDynamicSharedMemorySize, smem1);
    cudaFuncSetAttribute(k_conv2, cudaFuncAttributeMaxDynamicSharedMemorySize, smem2);

    k_conv1<<<dim3(7, 7, TT), 256, smem1>>>(in, w1);
    k_conv2<<<dim3(7, 7, TT * 10), 256, smem2>>>(w2, spk, pot);
}

// round 5
// speedup vs baseline: 1.3885x; 1.0953x over previous
#include <cuda_runtime.h>

#define TT  15
#define C1I 6
#define HI  224
#define WI  224
#define C1O 30
#define HP  114
#define WP  114
#define C2O 240
#define HO  112
#define WO  112

// Padded, pooled layer-1 spike map: (T, 30, 114, 114), border = 0 (pad 1).
__device__ float g_spk1[(size_t)TT * C1O * HP * WP];
// Conv2 weights padded for LDG.128: [240][30][3][4] = {w0,w1,w2,0}
__device__ float g_w2pad[(size_t)C2O * 30 * 3 * 4];

// ---------------------------------------------------------------------------
// Prep: pad conv2 weight rows to 4 floats.
// ---------------------------------------------------------------------------
__global__ __launch_bounds__(256) void k_prep(const float* __restrict__ w2) {
    int i = blockIdx.x * 256 + threadIdx.x;      // row = (oc*30+ic)*3+kh
    if (i < C2O * 30 * 3) {
        const float* s = w2 + i * 3;
        float4* d = (float4*)(g_w2pad + (size_t)i * 4);
        *d = make_float4(s[0], s[1], s[2], 0.0f);
    }
}

// ---------------------------------------------------------------------------
// Kernel 1: conv1 (5x5, pad 2) + fire(15) + maxpool 2x2 + pad 1, fused.
// ---------------------------------------------------------------------------
__global__ __launch_bounds__(256) void k_conv1(const float* __restrict__ in,
                                               const float* __restrict__ w1) {
    extern __shared__ float smem[];
    float* sIn = smem;                 // [6][36][37]
    float* sW  = smem + 6 * 36 * 37;   // [30*6*25] = 4500

    const int t   = blockIdx.z;
    const int X0  = blockIdx.x * 16;
    const int Y0  = blockIdx.y * 16;
    const int tid = threadIdx.x;

    for (int i = tid; i < 4500; i += 256) sW[i] = w1[i];

    const float* inT = in + (size_t)t * (C1I * HI * WI);
    for (int i = tid; i < 6 * 36 * 36; i += 256) {
        int c  = i % 36;
        int r  = (i / 36) % 36;
        int ic = i / (36 * 36);
        int gy = 2 * Y0 - 2 + r;
        int gx = 2 * X0 - 2 + c;
        float v = 0.0f;
        if ((unsigned)gy < (unsigned)HI && (unsigned)gx < (unsigned)WI)
            v = inT[(ic * HI + gy) * WI + gx];
        sIn[(ic * 36 + r) * 37 + c] = v;
    }
    __syncthreads();

    const int tx = tid & 15;
    const int ty = tid >> 4;
    float* outp = g_spk1 + (size_t)t * C1O * HP * WP
                + (size_t)(Y0 + ty + 1) * WP + (X0 + tx + 1);

    for (int cg = 0; cg < 5; cg++) {
        float pot[6][4];
#pragma unroll
        for (int u = 0; u < 6; u++)
#pragma unroll
            for (int q = 0; q < 4; q++) pot[u][q] = 0.0f;

        for (int ic = 0; ic < 6; ic++) {
            float p[6][6];
#pragma unroll
            for (int r = 0; r < 6; r++)
#pragma unroll
                for (int c = 0; c < 6; c++)
                    p[r][c] = sIn[(ic * 36 + 2 * ty + r) * 37 + 2 * tx + c];

#pragma unroll
            for (int u = 0; u < 6; u++) {
                const float* w = sW + ((cg * 6 + u) * 6 + ic) * 25;
#pragma unroll
                for (int kh = 0; kh < 5; kh++)
#pragma unroll
                    for (int kw = 0; kw < 5; kw++) {
                        float wv = w[kh * 5 + kw];
                        pot[u][0] = fmaf(p[kh    ][kw    ], wv, pot[u][0]);
                        pot[u][1] = fmaf(p[kh    ][kw + 1], wv, pot[u][1]);
                        pot[u][2] = fmaf(p[kh + 1][kw    ], wv, pot[u][2]);
                        pot[u][3] = fmaf(p[kh + 1][kw + 1], wv, pot[u][3]);
                    }
            }
        }
#pragma unroll
        for (int u = 0; u < 6; u++) {
            float m = fmaxf(fmaxf(pot[u][0], pot[u][1]),
                            fmaxf(pot[u][2], pot[u][3]));
            outp[(size_t)(cg * 6 + u) * HP * WP] = (m > 15.0f) ? 1.0f : 0.0f;
        }
    }
}

// ---------------------------------------------------------------------------
// 24 FMAs for one weight row across 8 output pixels (named regs, no arrays).
// ---------------------------------------------------------------------------
__device__ __forceinline__ void fma_row(float* a, float4 w,
        float v0, float v1, float v2, float v3, float v4,
        float v5, float v6, float v7, float v8, float v9) {
    a[0] = fmaf(v0, w.x, a[0]); a[0] = fmaf(v1, w.y, a[0]); a[0] = fmaf(v2, w.z, a[0]);
    a[1] = fmaf(v1, w.x, a[1]); a[1] = fmaf(v2, w.y, a[1]); a[1] = fmaf(v3, w.z, a[1]);
    a[2] = fmaf(v2, w.x, a[2]); a[2] = fmaf(v3, w.y, a[2]); a[2] = fmaf(v4, w.z, a[2]);
    a[3] = fmaf(v3, w.x, a[3]); a[3] = fmaf(v4, w.y, a[3]); a[3] = fmaf(v5, w.z, a[3]);
    a[4] = fmaf(v4, w.x, a[4]); a[4] = fmaf(v5, w.y, a[4]); a[4] = fmaf(v6, w.z, a[4]);
    a[5] = fmaf(v5, w.x, a[5]); a[5] = fmaf(v6, w.y, a[5]); a[5] = fmaf(v7, w.z, a[5]);
    a[6] = fmaf(v6, w.x, a[6]); a[6] = fmaf(v7, w.y, a[6]); a[6] = fmaf(v8, w.z, a[6]);
    a[7] = fmaf(v7, w.x, a[7]); a[7] = fmaf(v8, w.y, a[7]); a[7] = fmaf(v9, w.z, a[7]);
}

// ---------------------------------------------------------------------------
// Kernel 2: conv2 (3x3, 30->240) + fire(10), scalar FFMA.
// Block (256 thr): 16x16 px tile, 24 oc; only the input tile in smem (43.2KB
// -> 5 blocks/SM). Weights: broadcast __ldg of padded rows (warp-uniform).
// Thread: 8 px x 3 oc. Activation LDS.128 conflict-free (stride 20).
// ---------------------------------------------------------------------------
#define S2 20   // sIn row stride in floats

__global__ __launch_bounds__(256) void k_conv2(float* __restrict__ spk,
                                               float* __restrict__ pot) {
    extern __shared__ float smem[];
    float* sIn = smem;                   // [30][18][20] = 10800 floats (43.2KB)

    const int t   = blockIdx.z / 10;
    const int ocb = (blockIdx.z % 10) * 24;
    const int X0  = blockIdx.x * 16;
    const int Y0  = blockIdx.y * 16;
    const int tid = threadIdx.x;

    // Input tile: 30ch x 18x18 from padded pooled spike map.
    const float* sp = g_spk1 + (size_t)t * (C1O * HP * WP);
    for (int i = tid; i < 30 * 18 * 18; i += 256) {
        int c  = i % 18;
        int r  = (i / 18) % 18;
        int ic = i / (18 * 18);
        sIn[(ic * 18 + r) * S2 + c] = sp[(ic * HP + Y0 + r) * WP + X0 + c];
    }
    __syncthreads();

    const int ty = tid & 15;
    const int qx = (tid >> 4) & 1;
    const int g  = tid >> 5;             // 8 warps x 3 oc = 24 oc

    float acc[3][8];
#pragma unroll
    for (int u = 0; u < 3; u++)
#pragma unroll
        for (int p = 0; p < 8; p++) acc[u][p] = 0.0f;

    const float*  vb = sIn + ty * S2 + 8 * qx;
    const float4* wp = (const float4*)(g_w2pad + (size_t)(ocb + g * 3) * 360);

    for (int ic = 0; ic < 30; ic++) {
#pragma unroll
        for (int kh = 0; kh < 3; kh++) {
            float4 A = *(const float4*)(vb + kh * S2);
            float4 B = *(const float4*)(vb + kh * S2 + 4);
            float2 C = *(const float2*)(vb + kh * S2 + 8);
            float4 w0 = __ldg(wp + kh);        // oc u=0
            float4 w1 = __ldg(wp + 90 + kh);   // oc u=1  (30*3 rows)
            float4 w2 = __ldg(wp + 180 + kh);  // oc u=2
            fma_row(acc[0], w0, A.x, A.y, A.z, A.w, B.x, B.y, B.z, B.w, C.x, C.y);
            fma_row(acc[1], w1, A.x, A.y, A.z, A.w, B.x, B.y, B.z, B.w, C.x, C.y);
            fma_row(acc[2], w2, A.x, A.y, A.z, A.w, B.x, B.y, B.z, B.w, C.x, C.y);
        }
        vb += 18 * S2;
        wp += 3;
    }

    const int y = Y0 + ty;
    const int x = X0 + 8 * qx;
#pragma unroll
    for (int u = 0; u < 3; u++) {
        int oc = ocb + g * 3 + u;
        size_t base = (((size_t)t * C2O + oc) * HO + y) * WO + x;
        float4 sa, sb, pa, pb;
        sa.x = acc[u][0] > 10.0f ? 1.0f : 0.0f;  pa.x = acc[u][0] > 10.0f ? acc[u][0] : 0.0f;
        sa.y = acc[u][1] > 10.0f ? 1.0f : 0.0f;  pa.y = acc[u][1] > 10.0f ? acc[u][1] : 0.0f;
        sa.z = acc[u][2] > 10.0f ? 1.0f : 0.0f;  pa.z = acc[u][2] > 10.0f ? acc[u][2] : 0.0f;
        sa.w = acc[u][3] > 10.0f ? 1.0f : 0.0f;  pa.w = acc[u][3] > 10.0f ? acc[u][3] : 0.0f;
        sb.x = acc[u][4] > 10.0f ? 1.0f : 0.0f;  pb.x = acc[u][4] > 10.0f ? acc[u][4] : 0.0f;
        sb.y = acc[u][5] > 10.0f ? 1.0f : 0.0f;  pb.y = acc[u][5] > 10.0f ? acc[u][5] : 0.0f;
        sb.z = acc[u][6] > 10.0f ? 1.0f : 0.0f;  pb.z = acc[u][6] > 10.0f ? acc[u][6] : 0.0f;
        sb.w = acc[u][7] > 10.0f ? 1.0f : 0.0f;  pb.w = acc[u][7] > 10.0f ? acc[u][7] : 0.0f;
        *reinterpret_cast<float4*>(spk + base)     = sa;
        *reinterpret_cast<float4*>(spk + base + 4) = sb;
        *reinterpret_cast<float4*>(pot + base)     = pa;
        *reinterpret_cast<float4*>(pot + base + 4) = pb;
    }
}

// ---------------------------------------------------------------------------
extern "C" void kernel_launch(void* const* d_in, const int* in_sizes, int n_in,
                              void* d_out, int out_size) {
    const float* in = (const float*)d_in[0];
    const float* w1 = (const float*)d_in[1];
    const float* w2 = (const float*)d_in[2];
    // d_in[3] = max_layer, always 2 in this problem.

    float* spk = (float*)d_out;
    const size_t n2 = (size_t)TT * C2O * HO * WO;
    float* pot = spk + n2;

    void* sp1 = nullptr;
    cudaGetSymbolAddress(&sp1, g_spk1);
    cudaMemsetAsync(sp1, 0, sizeof(g_spk1), 0);

    const int smem1 = (6 * 36 * 37 + 4500) * (int)sizeof(float);   // 49,968 B
    const int smem2 = (30 * 18 * S2) * (int)sizeof(float);         // 43,200 B
    cudaFuncSetAttribute(k_conv1, cudaFuncAttributeMaxDynamicSharedMemorySize, smem1);
    cudaFuncSetAttribute(k_conv2, cudaFuncAttributeMaxDynamicSharedMemorySize, smem2);

    k_prep<<<(C2O * 30 * 3 + 255) / 256, 256>>>(w2);
    k_conv1<<<dim3(7, 7, TT), 256, smem1>>>(in, w1);
    k_conv2<<<dim3(7, 7, TT * 10), 256, smem2>>>(spk, pot);
}

// round 7
// speedup vs baseline: 2.2712x; 1.6357x over previous
#include <cuda_runtime.h>
#include <cuda_bf16.h>
#include <cstdint>

#define TT  15
#define C1I 6
#define HI  224
#define WI  224
#define C1O 30
#define HP  114
#define WP  114
#define C2O 240
#define HO  112
#define WO  112

// Layer-1 pooled spikes, channel-last bf16, padded: [t][y(114)][x(114)][32]
__device__ __align__(16) unsigned short g_spk1b[(size_t)TT * HP * WP * 32];
// Conv2 weights as mma.sync B-fragments:
// [s(18)][pass(2)][nh(2)][nt(15)][lane(32)] x uint2  (276,480 B)
__device__ __align__(16) uint2 g_Bfrag[18 * 2 * 2 * 15 * 32];

__device__ __forceinline__ uint32_t cvta_smem(const void* p) {
    uint32_t a;
    asm("{ .reg .u64 t; cvta.to.shared.u64 t, %1; cvt.u32.u64 %0, t; }"
        : "=r"(a) : "l"(p));
    return a;
}

// ---------------------------------------------------------------------------
// Prep: build B fragments (hi/lo split) for mma.sync m16n8k16 .row.col.
// b-frag: reg r, elem e -> k = (l&3)*2 + r*8 + e (within k16), n = l>>2.
// Global k = s*16 + k;  tap = k>>5 (kh*3+kw), ic = k&31 (pad 30->32).
// ---------------------------------------------------------------------------
__global__ __launch_bounds__(256) void k_prepB(const float* __restrict__ w2) {
    int i = blockIdx.x * 256 + threadIdx.x;
    if (i >= 18 * 2 * 2 * 15 * 32) return;
    int l  = i & 31;
    int nt = (i >> 5) % 15;
    int nh = (i / 480) & 1;
    int p  = (i / 960) & 1;
    int s  = i / 1920;
    int oc = nh * 120 + nt * 8 + (l >> 2);

    uint32_t r01[2];
#pragma unroll
    for (int r = 0; r < 2; r++) {
        uint32_t packed = 0;
#pragma unroll
        for (int e = 0; e < 2; e++) {
            int k  = s * 16 + (l & 3) * 2 + r * 8 + e;
            int tap = k >> 5, ic = k & 31;
            float w = (ic < 30) ? w2[(oc * 30 + ic) * 9 + tap] : 0.0f;
            __nv_bfloat16 hi = __float2bfloat16(w);
            __nv_bfloat16 v  = p ? __float2bfloat16(w - __bfloat162float(hi)) : hi;
            unsigned short b = *(unsigned short*)&v;
            packed |= (uint32_t)b << (16 * e);
        }
        r01[r] = packed;
    }
    g_Bfrag[i] = make_uint2(r01[0], r01[1]);
}

// ---------------------------------------------------------------------------
// Kernel 1: conv1 (5x5,pad2) + fire(15) + maxpool2x2 + pad1 ->
// channel-last bf16 spike map.
// ---------------------------------------------------------------------------
__global__ __launch_bounds__(256) void k_conv1(const float* __restrict__ in,
                                               const float* __restrict__ w1) {
    extern __shared__ float smem[];
    float* sIn = smem;                 // [6][36][37]
    float* sW  = smem + 6 * 36 * 37;   // 4500

    const int t   = blockIdx.z;
    const int X0  = blockIdx.x * 16;
    const int Y0  = blockIdx.y * 16;
    const int tid = threadIdx.x;

    for (int i = tid; i < 4500; i += 256) sW[i] = w1[i];

    const float* inT = in + (size_t)t * (C1I * HI * WI);
    for (int i = tid; i < 6 * 36 * 36; i += 256) {
        int c  = i % 36;
        int r  = (i / 36) % 36;
        int ic = i / (36 * 36);
        int gy = 2 * Y0 - 2 + r;
        int gx = 2 * X0 - 2 + c;
        float v = 0.0f;
        if ((unsigned)gy < (unsigned)HI && (unsigned)gx < (unsigned)WI)
            v = inT[(ic * HI + gy) * WI + gx];
        sIn[(ic * 36 + r) * 37 + c] = v;
    }
    __syncthreads();

    const int tx = tid & 15;
    const int ty = tid >> 4;

    unsigned int pk[16];
#pragma unroll
    for (int j = 0; j < 16; j++) pk[j] = 0u;

    for (int cg = 0; cg < 5; cg++) {
        float pot[6][4];
#pragma unroll
        for (int u = 0; u < 6; u++)
#pragma unroll
            for (int q = 0; q < 4; q++) pot[u][q] = 0.0f;

        for (int ic = 0; ic < 6; ic++) {
            float p[6][6];
#pragma unroll
            for (int r = 0; r < 6; r++)
#pragma unroll
                for (int c = 0; c < 6; c++)
                    p[r][c] = sIn[(ic * 36 + 2 * ty + r) * 37 + 2 * tx + c];

#pragma unroll
            for (int u = 0; u < 6; u++) {
                const float* w = sW + ((cg * 6 + u) * 6 + ic) * 25;
#pragma unroll
                for (int kh = 0; kh < 5; kh++)
#pragma unroll
                    for (int kw = 0; kw < 5; kw++) {
                        float wv = w[kh * 5 + kw];
                        pot[u][0] = fmaf(p[kh    ][kw    ], wv, pot[u][0]);
                        pot[u][1] = fmaf(p[kh    ][kw + 1], wv, pot[u][1]);
                        pot[u][2] = fmaf(p[kh + 1][kw    ], wv, pot[u][2]);
                        pot[u][3] = fmaf(p[kh + 1][kw + 1], wv, pot[u][3]);
                    }
            }
        }
#pragma unroll
        for (int u = 0; u < 6; u++) {
            float m = fmaxf(fmaxf(pot[u][0], pot[u][1]),
                            fmaxf(pot[u][2], pot[u][3]));
            unsigned int bit = (m > 15.0f) ? 0x3F80u : 0u;   // bf16 1.0
            pk[cg * 3 + (u >> 1)] |= bit << (16 * (u & 1));
        }
    }

    const int y = Y0 + ty + 1;
    const int x = X0 + tx + 1;
    uint4* dst = (uint4*)(g_spk1b + ((size_t)(t * HP + y) * WP + x) * 32);
    dst[0] = make_uint4(pk[0],  pk[1],  pk[2],  pk[3]);
    dst[1] = make_uint4(pk[4],  pk[5],  pk[6],  pk[7]);
    dst[2] = make_uint4(pk[8],  pk[9],  pk[10], pk[11]);
    dst[3] = make_uint4(pk[12], pk[13], pk[14], 0u);
}

// ---------------------------------------------------------------------------
// Kernel 2: conv2 via mma.sync implicit GEMM + fire(10).
// CTA (512 thr, 16 warps): 16x8 px tile (M=128), N=240, K=288 x {hi,lo}.
// Warp (mt 0-7, nh 0-1): M16 x N120 -> 15 n8-tiles, 60 f32 accum regs.
// A: im2col in smem, row = 9 taps x 32ch bf16 (576B, stride 592 = all-bank).
// B: fragment-ready LDG.64 from g_Bfrag (L1-resident, warps barrier-aligned).
// ---------------------------------------------------------------------------
#define ASTR 592
#define SMA_BYTES (128 * ASTR)

__global__ __launch_bounds__(512) void k_conv2(float* __restrict__ spk,
                                               float* __restrict__ pot) {
    extern __shared__ __align__(16) unsigned char sm[];
    const uint32_t smb = cvta_smem(sm);
    const int tid = threadIdx.x;
    const int wid = tid >> 5;
    const int l   = tid & 31;

    const int t   = blockIdx.z;
    const int OY0 = blockIdx.y * 8;
    const int OX0 = blockIdx.x * 16;

    // ---- Build A: rows m = py*16+px, cols k = tap*32+ic ----
    const unsigned short* spb = g_spk1b + (size_t)t * HP * WP * 32;
    for (int i = tid; i < 4608; i += 512) {
        int u = i & 3, tap = (i >> 2) % 9, m = i / 36;
        int kh = tap / 3, kw = tap - kh * 3;
        int py = m >> 4, px = m & 15;
        uint4 v = *(const uint4*)(spb +
            ((size_t)(OY0 + py + kh) * WP + (OX0 + px + kw)) * 32 + u * 8);
        *(uint4*)(sm + m * ASTR + tap * 64 + u * 16) = v;
    }
    __syncthreads();

    const int mt = wid & 7;
    const int nh = wid >> 3;

    // ldmatrix address: lane -> (matrix, row) pattern for m16k16 x4
    const uint32_t abase = smb
        + (mt * 16 + ((l >> 3) & 1) * 8 + (l & 7)) * ASTR
        + ((l >> 4) & 1) * 16;

    float c[15][4];
#pragma unroll
    for (int nt = 0; nt < 15; nt++)
#pragma unroll
        for (int j = 0; j < 4; j++) c[nt][j] = 0.0f;

    for (int s = 0; s < 18; s++) {
        __syncthreads();   // keep warps aligned -> B stays L1-hot
        uint32_t a0, a1, a2, a3;
        asm volatile("ldmatrix.sync.aligned.m8n8.x4.shared.b16 {%0,%1,%2,%3}, [%4];"
                     : "=r"(a0), "=r"(a1), "=r"(a2), "=r"(a3)
                     : "r"(abase + s * 32));
#pragma unroll
        for (int p = 0; p < 2; p++) {
            const uint2* bp = g_Bfrag + (((s * 2 + p) * 2 + nh) * 15) * 32 + l;
#pragma unroll
            for (int nt = 0; nt < 15; nt++) {
                uint2 b = __ldg(bp + nt * 32);
                asm volatile(
                    "mma.sync.aligned.m16n8k16.row.col.f32.bf16.bf16.f32 "
                    "{%0,%1,%2,%3}, {%4,%5,%6,%7}, {%8,%9}, {%0,%1,%2,%3};"
                    : "+f"(c[nt][0]), "+f"(c[nt][1]), "+f"(c[nt][2]), "+f"(c[nt][3])
                    : "r"(a0), "r"(a1), "r"(a2), "r"(a3), "r"(b.x), "r"(b.y));
            }
        }
    }

    // ---- Epilogue: fire(10), scatter stores ----
    const int g   = l >> 2;
    const int tig = l & 3;
    const int m0  = mt * 16 + g;
    const int m1  = m0 + 8;
    const int y0  = OY0 + (m0 >> 4), x0 = OX0 + (m0 & 15);
    const int y1  = OY0 + (m1 >> 4), x1 = OX0 + (m1 & 15);
    const size_t tb = (size_t)t * C2O * HO * WO;
    const size_t n2 = (size_t)TT * C2O * HO * WO;

#pragma unroll
    for (int nt = 0; nt < 15; nt++) {
        int oc0 = nh * 120 + nt * 8 + 2 * tig;
#pragma unroll
        for (int j = 0; j < 4; j++) {
            int   oc = oc0 + (j & 1);
            int   yy = (j < 2) ? y0 : y1;
            int   xx = (j < 2) ? x0 : x1;
            float a  = c[nt][j];
            size_t bi = tb + ((size_t)oc * HO + yy) * WO + xx;
            spk[bi]      = a > 10.0f ? 1.0f : 0.0f;
            spk[bi + n2] = a > 10.0f ? a : 0.0f;   // pot region
        }
    }
}

// ---------------------------------------------------------------------------
extern "C" void kernel_launch(void* const* d_in, const int* in_sizes, int n_in,
                              void* d_out, int out_size) {
    const float* in = (const float*)d_in[0];
    const float* w1 = (const float*)d_in[1];
    const float* w2 = (const float*)d_in[2];

    float* spk = (float*)d_out;
    const size_t n2 = (size_t)TT * C2O * HO * WO;
    float* pot = spk + n2;

    void* p1 = nullptr; cudaGetSymbolAddress(&p1, g_spk1b);
    cudaMemsetAsync(p1, 0, (size_t)TT * HP * WP * 32 * 2, 0);

    const int smem1 = (6 * 36 * 37 + 4500) * (int)sizeof(float);
    cudaFuncSetAttribute(k_conv1, cudaFuncAttributeMaxDynamicSharedMemorySize, smem1);
    cudaFuncSetAttribute(k_conv2, cudaFuncAttributeMaxDynamicSharedMemorySize, SMA_BYTES);

    k_prepB<<<(18 * 2 * 2 * 15 * 32 + 255) / 256, 256>>>(w2);
    k_conv1<<<dim3(7, 7, TT), 256, smem1>>>(in, w1);
    k_conv2<<<dim3(7, 14, TT), 512, SMA_BYTES>>>(spk, pot);
}

// round 8
// speedup vs baseline: 4.1002x; 1.8053x over previous
#include <cuda_runtime.h>
#include <cuda_bf16.h>
#include <cstdint>

#define TT  15
#define C1I 6
#define HI  224
#define WI  224
#define C1O 30
#define HP  114
#define WP  114
#define C2O 240
#define HO  112
#define WO  112

// Layer-1 pooled spikes, channel-last bf16, padded: [t][y(114)][x(114)][32]
__device__ __align__(16) unsigned short g_spk1b[(size_t)TT * HP * WP * 32];
// Conv1 B-fragments: [s(13)][nt(4)][lane(32)] uint2 (k = tap*8+ic, N=32)
__device__ __align__(16) uint2 g_Bf1[13 * 4 * 32];
// Conv2 B-fragments: [s(18)][nh(2)][nt(15)][lane(32)] uint2 (k = tap*32+ic)
__device__ __align__(16) uint2 g_Bf2[18 * 2 * 15 * 32];

__device__ __forceinline__ uint32_t cvta_smem(const void* p) {
    uint32_t a;
    asm("{ .reg .u64 t; cvta.to.shared.u64 t, %1; cvt.u32.u64 %0, t; }"
        : "=r"(a) : "l"(p));
    return a;
}
__device__ __forceinline__ unsigned short f2bf(float f) {
    __nv_bfloat16 b = __float2bfloat16(f);
    return *(unsigned short*)&b;
}

// ---------------------------------------------------------------------------
// Prep: build bf16 B-fragments for both convs (mma.sync m16n8k16 .row.col:
// lane l holds n = l>>2, k = (l&3)*2 + r*8 + e).
// ---------------------------------------------------------------------------
__global__ __launch_bounds__(256) void k_prep(const float* __restrict__ w1,
                                              const float* __restrict__ w2) {
    int i = blockIdx.x * 256 + threadIdx.x;
    if (i < 13 * 4 * 32) {                      // conv1
        int l = i & 31, nt = (i >> 5) & 3, s = i >> 7;
        int oc = nt * 8 + (l >> 2);
        uint32_t rr[2];
#pragma unroll
        for (int r = 0; r < 2; r++) {
            uint32_t pk = 0;
#pragma unroll
            for (int e = 0; e < 2; e++) {
                int k = s * 16 + (l & 3) * 2 + r * 8 + e;
                int tap = k >> 3, ic = k & 7;
                float w = (ic < 6 && tap < 25 && oc < 30)
                        ? w1[(oc * 6 + ic) * 25 + tap] : 0.0f;
                pk |= (uint32_t)f2bf(w) << (16 * e);
            }
            rr[r] = pk;
        }
        g_Bf1[i] = make_uint2(rr[0], rr[1]);
    } else if (i < 13 * 4 * 32 + 18 * 2 * 15 * 32) {  // conv2
        int j = i - 13 * 4 * 32;
        int l = j & 31, nt = (j >> 5) % 15, nh = (j / 480) & 1, s = j / 960;
        int oc = nh * 120 + nt * 8 + (l >> 2);
        uint32_t rr[2];
#pragma unroll
        for (int r = 0; r < 2; r++) {
            uint32_t pk = 0;
#pragma unroll
            for (int e = 0; e < 2; e++) {
                int k = s * 16 + (l & 3) * 2 + r * 8 + e;
                int tap = k >> 5, ic = k & 31;
                float w = (ic < 30) ? w2[(oc * 30 + ic) * 9 + tap] : 0.0f;
                pk |= (uint32_t)f2bf(w) << (16 * e);
            }
            rr[r] = pk;
        }
        g_Bf2[j] = make_uint2(rr[0], rr[1]);
    }
}

// ---------------------------------------------------------------------------
// Kernel 1: conv1 via mma.sync + fire(15) + maxpool 2x2 -> channel-last bf16.
// CTA (256 thr, 8 warps): 16x16 conv-px tile (M=256), N=32, K=208 (26 taps x 8ic).
// A: halo image [20][20][8ch] bf16 in smem; k16-step s = taps {2s, 2s+1} via
// tap-shifted ldmatrix.x4 (no im2col). Warp: py-rows {2w, 2w+1}.
// ---------------------------------------------------------------------------
#define C1_IMG   0
#define C1_C     6400
#define C1_SMEM  (6400 + 32768)

__global__ __launch_bounds__(256) void k_conv1(const float* __restrict__ in) {
    extern __shared__ __align__(16) unsigned char sm[];
    const uint32_t smb = cvta_smem(sm);
    float* sC = (float*)(sm + C1_C);           // [py16][px16][oc32]

    const int t   = blockIdx.z;
    const int X0  = blockIdx.x * 16;           // conv-px base
    const int Y0  = blockIdx.y * 16;
    const int tid = threadIdx.x;
    const int wid = tid >> 5;
    const int l   = tid & 31;

    // Build halo image: [ly 20][lx 20][8] bf16 (ic 6 + 2 zero)
    const float* inT = in + (size_t)t * (C1I * HI * WI);
    for (int i = tid; i < 400; i += 256) {
        int ly = i / 20, lx = i % 20;
        int gy = Y0 - 2 + ly, gx = X0 - 2 + lx;
        unsigned short row[8];
        bool ok = (unsigned)gy < (unsigned)HI && (unsigned)gx < (unsigned)WI;
#pragma unroll
        for (int ic = 0; ic < 6; ic++)
            row[ic] = ok ? f2bf(inT[(ic * HI + gy) * WI + gx]) : 0;
        row[6] = 0; row[7] = 0;
        *(uint4*)(sm + C1_IMG + i * 16) = *(uint4*)row;
    }
    __syncthreads();

    float c[2][4][4];
#pragma unroll
    for (int i = 0; i < 2; i++)
#pragma unroll
        for (int nt = 0; nt < 4; nt++)
#pragma unroll
            for (int j = 0; j < 4; j++) c[i][nt][j] = 0.0f;

    const int pxl  = l & 15;          // A row (px within tile)
    const int tsel = l >> 4;          // which tap of the k16 step

    for (int s = 0; s < 13; s++) {
        int tp = 2 * s + tsel; if (tp > 24) tp = 24;   // tap25: w=0, clamp addr
        int kh = tp / 5, kw = tp - 5 * kh;
#pragma unroll
        for (int i = 0; i < 2; i++) {
            int py = 2 * wid + i;
            uint32_t addr = smb + C1_IMG + ((py + kh) * 20 + pxl + kw) * 16;
            uint32_t a0, a1, a2, a3;
            asm volatile("ldmatrix.sync.aligned.m8n8.x4.shared.b16 {%0,%1,%2,%3}, [%4];"
                         : "=r"(a0), "=r"(a1), "=r"(a2), "=r"(a3) : "r"(addr));
            const uint2* bp = g_Bf1 + s * 128 + l;
#pragma unroll
            for (int nt = 0; nt < 4; nt++) {
                uint2 b = __ldg(bp + nt * 32);
                asm volatile(
                    "mma.sync.aligned.m16n8k16.row.col.f32.bf16.bf16.f32 "
                    "{%0,%1,%2,%3}, {%4,%5,%6,%7}, {%8,%9}, {%0,%1,%2,%3};"
                    : "+f"(c[i][nt][0]), "+f"(c[i][nt][1]),
                      "+f"(c[i][nt][2]), "+f"(c[i][nt][3])
                    : "r"(a0), "r"(a1), "r"(a2), "r"(a3), "r"(b.x), "r"(b.y));
            }
        }
    }

    // Dump C to smem: [py][px][oc]
#pragma unroll
    for (int i = 0; i < 2; i++) {
        int py = 2 * wid + i;
        int px0 = l >> 2, oc0 = 2 * (l & 3);
#pragma unroll
        for (int nt = 0; nt < 4; nt++) {
            *(float2*)(sC + (py * 16 + px0) * 32 + nt * 8 + oc0)
                = make_float2(c[i][nt][0], c[i][nt][1]);
            *(float2*)(sC + (py * 16 + px0 + 8) * 32 + nt * 8 + oc0)
                = make_float2(c[i][nt][2], c[i][nt][3]);
        }
    }
    __syncthreads();

    // Pool 2x2 + fire(15) -> packed bf16 channel-last store
    {
        int ocq = tid & 3;                 // 8 oc each
        int ppx = (tid >> 2) & 7;
        int ppy = tid >> 5;
        uint32_t w[4];
#pragma unroll
        for (int u = 0; u < 4; u++) {
            uint32_t word = 0;
#pragma unroll
            for (int h = 0; h < 2; h++) {
                int oc = ocq * 8 + u * 2 + h;
                const float* p = sC + ((2 * ppy) * 16 + 2 * ppx) * 32 + oc;
                float m = fmaxf(fmaxf(p[0], p[32]), fmaxf(p[16 * 32], p[17 * 32]));
                if (m > 15.0f) word |= 0x3F80u << (16 * h);
            }
            w[u] = word;
        }
        int y = blockIdx.y * 8 + ppy + 1;
        int x = blockIdx.x * 8 + ppx + 1;
        *(uint4*)(g_spk1b + ((size_t)(t * HP + y) * WP + x) * 32 + ocq * 8)
            = make_uint4(w[0], w[1], w[2], w[3]);
    }
}

// ---------------------------------------------------------------------------
// Kernel 2: conv2 via mma.sync (single bf16 pass) + fire(10).
// CTA (512 thr, 16 warps): 16x8 px (M=128), N=240, K=288.
// ---------------------------------------------------------------------------
#define ASTR 592
#define SMA_BYTES (128 * ASTR)

__global__ __launch_bounds__(512) void k_conv2(float* __restrict__ spk,
                                               float* __restrict__ pot) {
    extern __shared__ __align__(16) unsigned char sm[];
    const uint32_t smb = cvta_smem(sm);
    const int tid = threadIdx.x;
    const int wid = tid >> 5;
    const int l   = tid & 31;

    const int t   = blockIdx.z;
    const int OY0 = blockIdx.y * 8;
    const int OX0 = blockIdx.x * 16;

    const unsigned short* spb = g_spk1b + (size_t)t * HP * WP * 32;
    for (int i = tid; i < 4608; i += 512) {
        int u = i & 3, tap = (i >> 2) % 9, m = i / 36;
        int kh = tap / 3, kw = tap - kh * 3;
        int py = m >> 4, px = m & 15;
        uint4 v = *(const uint4*)(spb +
            ((size_t)(OY0 + py + kh) * WP + (OX0 + px + kw)) * 32 + u * 8);
        *(uint4*)(sm + m * ASTR + tap * 64 + u * 16) = v;
    }
    __syncthreads();

    const int mt = wid & 7;
    const int nh = wid >> 3;

    const uint32_t abase = smb
        + (mt * 16 + ((l >> 3) & 1) * 8 + (l & 7)) * ASTR
        + ((l >> 4) & 1) * 16;

    float c[15][4];
#pragma unroll
    for (int nt = 0; nt < 15; nt++)
#pragma unroll
        for (int j = 0; j < 4; j++) c[nt][j] = 0.0f;

    for (int s = 0; s < 18; s++) {
        __syncthreads();
        uint32_t a0, a1, a2, a3;
        asm volatile("ldmatrix.sync.aligned.m8n8.x4.shared.b16 {%0,%1,%2,%3}, [%4];"
                     : "=r"(a0), "=r"(a1), "=r"(a2), "=r"(a3)
                     : "r"(abase + s * 32));
        const uint2* bp = g_Bf2 + ((s * 2 + nh) * 15) * 32 + l;
#pragma unroll
        for (int nt = 0; nt < 15; nt++) {
            uint2 b = __ldg(bp + nt * 32);
            asm volatile(
                "mma.sync.aligned.m16n8k16.row.col.f32.bf16.bf16.f32 "
                "{%0,%1,%2,%3}, {%4,%5,%6,%7}, {%8,%9}, {%0,%1,%2,%3};"
                : "+f"(c[nt][0]), "+f"(c[nt][1]), "+f"(c[nt][2]), "+f"(c[nt][3])
                : "r"(a0), "r"(a1), "r"(a2), "r"(a3), "r"(b.x), "r"(b.y));
        }
    }

    const int g   = l >> 2;
    const int tig = l & 3;
    const int m0  = mt * 16 + g;
    const int m1  = m0 + 8;
    const int y0  = OY0 + (m0 >> 4), x0 = OX0 + (m0 & 15);
    const int y1  = OY0 + (m1 >> 4), x1 = OX0 + (m1 & 15);
    const size_t tb = (size_t)t * C2O * HO * WO;
    const size_t n2 = (size_t)TT * C2O * HO * WO;

#pragma unroll
    for (int nt = 0; nt < 15; nt++) {
        int oc0 = nh * 120 + nt * 8 + 2 * tig;
#pragma unroll
        for (int j = 0; j < 4; j++) {
            int   oc = oc0 + (j & 1);
            int   yy = (j < 2) ? y0 : y1;
            int   xx = (j < 2) ? x0 : x1;
            float a  = c[nt][j];
            size_t bi = tb + ((size_t)oc * HO + yy) * WO + xx;
            spk[bi]      = a > 10.0f ? 1.0f : 0.0f;
            spk[bi + n2] = a > 10.0f ? a : 0.0f;
        }
    }
}

// ---------------------------------------------------------------------------
extern "C" void kernel_launch(void* const* d_in, const int* in_sizes, int n_in,
                              void* d_out, int out_size) {
    const float* in = (const float*)d_in[0];
    const float* w1 = (const float*)d_in[1];
    const float* w2 = (const float*)d_in[2];

    float* spk = (float*)d_out;
    const size_t n2 = (size_t)TT * C2O * HO * WO;
    float* pot = spk + n2;

    void* p1 = nullptr; cudaGetSymbolAddress(&p1, g_spk1b);
    cudaMemsetAsync(p1, 0, (size_t)TT * HP * WP * 32 * 2, 0);

    cudaFuncSetAttribute(k_conv1, cudaFuncAttributeMaxDynamicSharedMemorySize, C1_SMEM);
    cudaFuncSetAttribute(k_conv2, cudaFuncAttributeMaxDynamicSharedMemorySize, SMA_BYTES);

    const int nprep = 13 * 4 * 32 + 18 * 2 * 15 * 32;
    k_prep<<<(nprep + 255) / 256, 256>>>(w1, w2);
    k_conv1<<<dim3(14, 14, TT), 256, C1_SMEM>>>(in);
    k_conv2<<<dim3(7, 14, TT), 512, SMA_BYTES>>>(spk, pot);
}